// round 6
// baseline (speedup 1.0000x reference)
#include <cuda_runtime.h>
#include <cuda_bf16.h>
#include <math.h>
#include <stdint.h>

#define SEQ   1024
#define EMB   1024
#define BATCH 2
#define MHEAD 16      // total heads (M*H)
#define HD    64      // head dim
#define E3    (3*EMB)

// ---------------- scratch (allocation-free rule: __device__ globals) --------
__device__ float g_qkv[(size_t)BATCH*SEQ*E3];        // [2048][3072]  q|k|v
__device__ float g_att[(size_t)BATCH*MHEAD*SEQ*SEQ]; // att, then p in-place
__device__ float g_ao [(size_t)BATCH*SEQ*EMB];       // attention out pre-proj

// ===================== helpers ==============================================
__device__ __forceinline__ uint32_t smem_u32(const void* p) {
    uint32_t a;
    asm("{ .reg .u64 t; cvta.to.shared.u64 t, %1; cvt.u32.u64 %0, t; }"
        : "=r"(a) : "l"(p));
    return a;
}
__device__ __forceinline__ void ldsm4(uint32_t* r, uint32_t addr) {
    asm volatile("ldmatrix.sync.aligned.m8n8.x4.shared.b16 {%0,%1,%2,%3}, [%4];"
                 : "=r"(r[0]), "=r"(r[1]), "=r"(r[2]), "=r"(r[3]) : "r"(addr));
}
__device__ __forceinline__ void mma16816(float* d, const uint32_t* a,
                                         const uint32_t* b) {
    asm volatile("mma.sync.aligned.m16n8k16.row.col.f32.bf16.bf16.f32 "
                 "{%0,%1,%2,%3}, {%4,%5,%6,%7}, {%8,%9}, {%0,%1,%2,%3};"
                 : "+f"(d[0]), "+f"(d[1]), "+f"(d[2]), "+f"(d[3])
                 : "r"(a[0]), "r"(a[1]), "r"(a[2]), "r"(a[3]),
                   "r"(b[0]), "r"(b[1]));
}
__device__ __forceinline__ uint32_t pack_bf16(float x, float y) {
    __nv_bfloat162 p;
    p.x = __float2bfloat16(x);
    p.y = __float2bfloat16(y);
    return *(uint32_t*)&p;
}
__device__ __forceinline__ void split_lo(uint32_t hi, float x, float y,
                                         uint32_t* lo) {
    __nv_bfloat162* h = (__nv_bfloat162*)&hi;
    *lo = pack_bf16(x - __bfloat162float(h->x), y - __bfloat162float(h->y));
}

#define PADK 40

// ========== bf16x3 NT GEMM via mma.sync: C[M][N] = A[M][K] @ B[N][K]^T ======
// Block tile 128x128, K-chunk 32. 8 warps: 4(m) x 2(n), warp tile 32x64.
__global__ void __launch_bounds__(256)
gemm_mma(const float* __restrict__ A, const float* __restrict__ B,
         float* __restrict__ C, int N, int K) {
    __shared__ __align__(16) __nv_bfloat16 sAh[128 * PADK], sAl[128 * PADK],
                                           sBh[128 * PADK], sBl[128 * PADK];
    const int tid = threadIdx.x, lane = tid & 31, wid = tid >> 5;
    const int wm = wid & 3, wn = wid >> 2;
    const int bm = blockIdx.y * 128, bn = blockIdx.x * 128;

    const uint32_t sb_ah = smem_u32(sAh), sb_al = smem_u32(sAl);
    const uint32_t sb_bh = smem_u32(sBh), sb_bl = smem_u32(sBl);

    float acc[2][8][4] = {};
    float2 av[8], bv[8];

    auto load_stage = [&](int kt) {
        #pragma unroll
        for (int j = 0; j < 8; j++) {
            int idx = j * 256 + tid;
            int row = idx >> 4, c2 = idx & 15;
            av[j] = *(const float2*)&A[(size_t)(bm + row) * K + kt + c2 * 2];
            bv[j] = *(const float2*)&B[(size_t)(bn + row) * K + kt + c2 * 2];
        }
    };
    auto store_stage = [&]() {
        #pragma unroll
        for (int j = 0; j < 8; j++) {
            int idx = j * 256 + tid;
            int row = idx >> 4, c2 = idx & 15;
            int off = row * PADK + c2 * 2;
            uint32_t ah = pack_bf16(av[j].x, av[j].y);
            *(uint32_t*)&sAh[off] = ah;
            split_lo(ah, av[j].x, av[j].y, (uint32_t*)&sAl[off]);
            uint32_t bh = pack_bf16(bv[j].x, bv[j].y);
            *(uint32_t*)&sBh[off] = bh;
            split_lo(bh, bv[j].x, bv[j].y, (uint32_t*)&sBl[off]);
        }
    };

    const int nch = K / 32;
    load_stage(0);
    for (int ch = 0; ch < nch; ch++) {
        store_stage();
        __syncthreads();
        if (ch + 1 < nch) load_stage((ch + 1) * 32);

        #pragma unroll
        for (int ks = 0; ks < 2; ks++) {
            uint32_t ahf[2][4], alf[2][4];
            const int arow = wm * 32 + (lane & 15);
            const int acol = ks * 16 + (lane >> 4) * 8;
            #pragma unroll
            for (int mf = 0; mf < 2; mf++) {
                uint32_t ad = (uint32_t)(((arow + mf * 16) * PADK + acol) * 2);
                ldsm4(ahf[mf], sb_ah + ad);
                ldsm4(alf[mf], sb_al + ad);
            }
            const int brow = wn * 64 + ((lane >> 4) << 3) + (lane & 7);
            const int bcol = ks * 16 + ((lane >> 3) & 1) * 8;
            #pragma unroll
            for (int nf2 = 0; nf2 < 4; nf2++) {
                uint32_t bd = (uint32_t)(((brow + nf2 * 16) * PADK + bcol) * 2);
                uint32_t bhf[4], blf[4];
                ldsm4(bhf, sb_bh + bd);
                ldsm4(blf, sb_bl + bd);
                #pragma unroll
                for (int h = 0; h < 2; h++) {
                    #pragma unroll
                    for (int mf = 0; mf < 2; mf++) {
                        float* d = acc[mf][nf2 * 2 + h];
                        mma16816(d, ahf[mf], bhf + 2 * h);
                        mma16816(d, ahf[mf], blf + 2 * h);
                        mma16816(d, alf[mf], bhf + 2 * h);
                    }
                }
            }
        }
        __syncthreads();
    }

    #pragma unroll
    for (int mf = 0; mf < 2; mf++) {
        const int r = bm + wm * 32 + mf * 16 + (lane >> 2);
        #pragma unroll
        for (int nf = 0; nf < 8; nf++) {
            const int c = bn + wn * 64 + nf * 8 + (lane & 3) * 2;
            *(float2*)&C[(size_t)r * N + c] =
                make_float2(acc[mf][nf][0], acc[mf][nf][1]);
            *(float2*)&C[(size_t)(r + 8) * N + c] =
                make_float2(acc[mf][nf][2], acc[mf][nf][3]);
        }
    }
}

// ========== att via mma: att = mask(Q K^T / 64); arc = sigmoid(att) =========
// 128x128 score tiles. grid (S/128 k-tiles, S/128 q-tiles, B*MHEAD).
__global__ void __launch_bounds__(256)
att_mma(const int* __restrict__ mask_head, const int* __restrict__ mask_child,
        float* __restrict__ arc) {
    const int bh = blockIdx.z, b = bh >> 4, head = bh & 15;
    const int q0 = blockIdx.y * 128, k0 = blockIdx.x * 128;
    const int tid = threadIdx.x, lane = tid & 31, wid = tid >> 5;
    const int wm = wid & 3, wn = wid >> 2;

    float* attp = g_att + (size_t)bh * SEQ * SEQ;
    float* arcp = arc + (size_t)bh * SEQ * SEQ;

    if (k0 > q0) {                     // tile fully above causal diagonal
        #pragma unroll
        for (int j = 0; j < 16; j++) { // 4096 float4 / 256 threads
            int i = j * 256 + tid;
            int r = i >> 5, c = (i & 31) * 4;
            size_t idx = (size_t)(q0 + r) * SEQ + k0 + c;
            *(float4*)&attp[idx] = make_float4(-INFINITY, -INFINITY,
                                               -INFINITY, -INFINITY);
            *(float4*)&arcp[idx] = make_float4(0.f, 0.f, 0.f, 0.f);
        }
        return;
    }

    __shared__ __align__(16) __nv_bfloat16 sAh[128 * PADK], sAl[128 * PADK],
                                           sBh[128 * PADK], sBl[128 * PADK];
    const uint32_t sb_ah = smem_u32(sAh), sb_al = smem_u32(sAl);
    const uint32_t sb_bh = smem_u32(sBh), sb_bl = smem_u32(sBl);

    const float* qbase = g_qkv + ((size_t)b * SEQ + q0) * E3 + head * HD;
    const float* kbase = g_qkv + ((size_t)b * SEQ + k0) * E3 + EMB + head * HD;

    float acc[2][8][4] = {};
    for (int ch = 0; ch < 2; ch++) {            // HD=64 in two 32-chunks
        const int kt = ch * 32;
        #pragma unroll
        for (int j = 0; j < 8; j++) {
            int idx = j * 256 + tid;
            int row = idx >> 4, c2 = idx & 15;
            int off = row * PADK + c2 * 2;
            float2 av = *(const float2*)&qbase[(size_t)row * E3 + kt + c2 * 2];
            uint32_t ah = pack_bf16(av.x, av.y);
            *(uint32_t*)&sAh[off] = ah;
            split_lo(ah, av.x, av.y, (uint32_t*)&sAl[off]);
            float2 bv = *(const float2*)&kbase[(size_t)row * E3 + kt + c2 * 2];
            uint32_t bhh = pack_bf16(bv.x, bv.y);
            *(uint32_t*)&sBh[off] = bhh;
            split_lo(bhh, bv.x, bv.y, (uint32_t*)&sBl[off]);
        }
        __syncthreads();
        #pragma unroll
        for (int ks = 0; ks < 2; ks++) {
            uint32_t ahf[2][4], alf[2][4];
            const int arow = wm * 32 + (lane & 15);
            const int acol = ks * 16 + (lane >> 4) * 8;
            #pragma unroll
            for (int mf = 0; mf < 2; mf++) {
                uint32_t ad = (uint32_t)(((arow + mf * 16) * PADK + acol) * 2);
                ldsm4(ahf[mf], sb_ah + ad);
                ldsm4(alf[mf], sb_al + ad);
            }
            const int brow = wn * 64 + ((lane >> 4) << 3) + (lane & 7);
            const int bcol = ks * 16 + ((lane >> 3) & 1) * 8;
            #pragma unroll
            for (int nf2 = 0; nf2 < 4; nf2++) {
                uint32_t bd = (uint32_t)(((brow + nf2 * 16) * PADK + bcol) * 2);
                uint32_t bhf[4], blf[4];
                ldsm4(bhf, sb_bh + bd);
                ldsm4(blf, sb_bl + bd);
                #pragma unroll
                for (int h = 0; h < 2; h++) {
                    #pragma unroll
                    for (int mf = 0; mf < 2; mf++) {
                        float* d = acc[mf][nf2 * 2 + h];
                        mma16816(d, ahf[mf], bhf + 2 * h);
                        mma16816(d, ahf[mf], blf + 2 * h);
                        mma16816(d, alf[mf], bhf + 2 * h);
                    }
                }
            }
        }
        __syncthreads();
    }

    // epilogue: scale, causal+mask, att/-inf, arc/sigmoid
    const int* msk = ((head >> 3) == 0 ? mask_head : mask_child)
                     + (size_t)b * SEQ * SEQ;
    #pragma unroll
    for (int mf = 0; mf < 2; mf++) {
        #pragma unroll
        for (int half = 0; half < 2; half++) {
            const int qi = q0 + wm * 32 + mf * 16 + (lane >> 2) + half * 8;
            #pragma unroll
            for (int nf = 0; nf < 8; nf++) {
                const int kj = k0 + wn * 64 + nf * 8 + (lane & 3) * 2;
                const size_t idx = (size_t)qi * SEQ + kj;
                const int2 mv = *(const int2*)&msk[idx];
                float2 oa, og;
                #pragma unroll
                for (int e = 0; e < 2; e++) {
                    float val = acc[mf][nf][half * 2 + e] * (1.0f / 64.0f);
                    bool valid = (kj + e <= qi) && ((e ? mv.y : mv.x) != 0);
                    (&oa.x)[e] = valid ? val : -INFINITY;
                    (&og.x)[e] = valid ? 1.0f / (1.0f + __expf(-val)) : 0.0f;
                }
                *(float2*)&attp[idx] = oa;
                *(float2*)&arcp[idx] = og;
            }
        }
    }
}

// ---------------- softmax over rows (in-place on g_att) ---------------------
__global__ void softmax_kernel() {
    const int row = blockIdx.x;
    float* p = g_att + (size_t)row * SEQ;
    const int tid = threadIdx.x;               // 256
    float v[4];
    float mx = -INFINITY;
    #pragma unroll
    for (int i = 0; i < 4; i++) { v[i] = p[tid + 256 * i]; mx = fmaxf(mx, v[i]); }
    __shared__ float red[256];
    red[tid] = mx; __syncthreads();
    for (int s = 128; s > 0; s >>= 1) {
        if (tid < s) red[tid] = fmaxf(red[tid], red[tid + s]);
        __syncthreads();
    }
    mx = red[0]; __syncthreads();
    if (mx == -INFINITY) {
        #pragma unroll
        for (int i = 0; i < 4; i++) p[tid + 256 * i] = 0.0f;
        return;
    }
    float sum = 0.0f;
    #pragma unroll
    for (int i = 0; i < 4; i++) { v[i] = __expf(v[i] - mx); sum += v[i]; }
    red[tid] = sum; __syncthreads();
    for (int s = 128; s > 0; s >>= 1) {
        if (tid < s) red[tid] += red[tid + s];
        __syncthreads();
    }
    float inv = 1.0f / red[0];
    #pragma unroll
    for (int i = 0; i < 4; i++) p[tid + 256 * i] = v[i] * inv;
}

// ========== PV via mma: ao[q, head*64+c] = sum_k P[q,k] V[k,c] ==============
// grid (S/128 q-tiles, B*MHEAD). Output tile 128x64. Warp tile 32x32.
__global__ void __launch_bounds__(256)
pv_mma() {
    const int bh = blockIdx.y, b = bh >> 4, head = bh & 15;
    const int q0 = blockIdx.x * 128;
    const int tid = threadIdx.x, lane = tid & 31, wid = tid >> 5;
    const int wm = wid & 3, wn = wid >> 2;

    const float* pbase = g_att + (size_t)bh * SEQ * SEQ + (size_t)q0 * SEQ;
    const float* vbase = g_qkv + (size_t)b * SEQ * E3 + 2 * EMB + head * HD;

    __shared__ __align__(16) __nv_bfloat16 sPh[128 * PADK], sPl[128 * PADK],
                                           sVh[64 * PADK],  sVl[64 * PADK];
    const uint32_t sb_ph = smem_u32(sPh), sb_pl = smem_u32(sPl);
    const uint32_t sb_vh = smem_u32(sVh), sb_vl = smem_u32(sVl);

    float acc[2][4][4] = {};
    const int nch = (q0 + 128) / 32;            // causal: k <= q0+127
    for (int ch = 0; ch < nch; ch++) {
        const int kt = ch * 32;
        // P chunk: 128 q-rows x 32 k-cols
        #pragma unroll
        for (int j = 0; j < 8; j++) {
            int idx = j * 256 + tid;
            int row = idx >> 4, c2 = idx & 15;
            int off = row * PADK + c2 * 2;
            float2 pv = *(const float2*)&pbase[(size_t)row * SEQ + kt + c2 * 2];
            uint32_t ph = pack_bf16(pv.x, pv.y);
            *(uint32_t*)&sPh[off] = ph;
            split_lo(ph, pv.x, pv.y, (uint32_t*)&sPl[off]);
        }
        // V chunk transposed: V[kt+k][c] -> sV[c*PADK + k];  32 k x 64 c
        #pragma unroll
        for (int j = 0; j < 2; j++) {
            int idx = j * 256 + tid;            // 512 float4 = 32 rows x 16
            int k = idx >> 4, c4 = (idx & 15) * 4;
            float4 vv = *(const float4*)&vbase[(size_t)(kt + k) * E3 + c4];
            #pragma unroll
            for (int e = 0; e < 4; e++) {
                float f = (&vv.x)[e];
                __nv_bfloat16 h = __float2bfloat16(f);
                sVh[(c4 + e) * PADK + k] = h;
                sVl[(c4 + e) * PADK + k] =
                    __float2bfloat16(f - __bfloat162float(h));
            }
        }
        __syncthreads();
        #pragma unroll
        for (int ks = 0; ks < 2; ks++) {
            uint32_t ahf[2][4], alf[2][4];
            const int arow = wm * 32 + (lane & 15);
            const int acol = ks * 16 + (lane >> 4) * 8;
            #pragma unroll
            for (int mf = 0; mf < 2; mf++) {
                uint32_t ad = (uint32_t)(((arow + mf * 16) * PADK + acol) * 2);
                ldsm4(ahf[mf], sb_ph + ad);
                ldsm4(alf[mf], sb_pl + ad);
            }
            const int brow = wn * 32 + ((lane >> 4) << 3) + (lane & 7);
            const int bcol = ks * 16 + ((lane >> 3) & 1) * 8;
            #pragma unroll
            for (int nf2 = 0; nf2 < 2; nf2++) {
                uint32_t bd = (uint32_t)(((brow + nf2 * 16) * PADK + bcol) * 2);
                uint32_t bhf[4], blf[4];
                ldsm4(bhf, sb_vh + bd);
                ldsm4(blf, sb_vl + bd);
                #pragma unroll
                for (int h = 0; h < 2; h++) {
                    #pragma unroll
                    for (int mf = 0; mf < 2; mf++) {
                        float* d = acc[mf][nf2 * 2 + h];
                        mma16816(d, ahf[mf], bhf + 2 * h);
                        mma16816(d, ahf[mf], blf + 2 * h);
                        mma16816(d, alf[mf], bhf + 2 * h);
                    }
                }
            }
        }
        __syncthreads();
    }

    #pragma unroll
    for (int mf = 0; mf < 2; mf++) {
        const int r = q0 + wm * 32 + mf * 16 + (lane >> 2);
        #pragma unroll
        for (int nf = 0; nf < 4; nf++) {
            const int c = head * HD + wn * 32 + nf * 8 + (lane & 3) * 2;
            *(float2*)&g_ao[(size_t)(b * SEQ + r) * EMB + c] =
                make_float2(acc[mf][nf][0], acc[mf][nf][1]);
            *(float2*)&g_ao[(size_t)(b * SEQ + r + 8) * EMB + c] =
                make_float2(acc[mf][nf][2], acc[mf][nf][3]);
        }
    }
}

// ---------------- launch ----------------------------------------------------
extern "C" void kernel_launch(void* const* d_in, const int* in_sizes, int n_in,
                              void* d_out, int out_size) {
    const float* x      = (const float*)d_in[0];
    const float* w_qkv  = (const float*)d_in[1];
    const float* w_proj = (const float*)d_in[2];
    const int*   m_head  = (const int*)d_in[3];
    const int*   m_child = (const int*)d_in[4];

    float* out = (float*)d_out;
    const size_t out_elems = (size_t)BATCH * SEQ * EMB;
    float* arc = out + out_elems;

    float *p_qkv, *p_ao;
    cudaGetSymbolAddress((void**)&p_qkv, g_qkv);
    cudaGetSymbolAddress((void**)&p_ao,  g_ao);

    // 1) QKV = X @ Wqkv^T : [2048,3072]  (bf16x3 mma.sync)
    gemm_mma<<<dim3(E3 / 128, BATCH * SEQ / 128), 256>>>(
        x, w_qkv, p_qkv, E3, EMB);

    // 2) scores + mask + sigmoid side-output  (bf16x3 mma.sync)
    att_mma<<<dim3(SEQ / 128, SEQ / 128, BATCH * MHEAD), 256>>>(
        m_head, m_child, arc);

    // 3) row softmax (in place)
    softmax_kernel<<<BATCH * MHEAD * SEQ, 256>>>();

    // 4) P @ V  (bf16x3 mma.sync)
    pv_mma<<<dim3(SEQ / 128, BATCH * MHEAD), 256>>>();

    // 5) out = AO @ Wproj^T  (bf16x3 mma.sync)
    gemm_mma<<<dim3(EMB / 128, BATCH * SEQ / 128), 256>>>(
        p_ao, w_proj, out, EMB, EMB);
}

// round 7
// speedup vs baseline: 1.0909x; 1.0909x over previous
#include <cuda_runtime.h>
#include <cuda_bf16.h>
#include <math.h>
#include <stdint.h>

#define SEQ   1024
#define EMB   1024
#define BATCH 2
#define MHEAD 16      // total heads (M*H)
#define HD    64      // head dim
#define E3    (3*EMB)

// ---------------- scratch (allocation-free rule: __device__ globals) --------
__device__ float g_qkv[(size_t)BATCH*SEQ*E3];   // [2048][3072]  q|k|v
__device__ float g_ao [(size_t)BATCH*SEQ*EMB];  // attention out pre-proj

// ===================== helpers ==============================================
__device__ __forceinline__ uint32_t smem_u32(const void* p) {
    uint32_t a;
    asm("{ .reg .u64 t; cvta.to.shared.u64 t, %1; cvt.u32.u64 %0, t; }"
        : "=r"(a) : "l"(p));
    return a;
}
__device__ __forceinline__ void ldsm4(uint32_t* r, uint32_t addr) {
    asm volatile("ldmatrix.sync.aligned.m8n8.x4.shared.b16 {%0,%1,%2,%3}, [%4];"
                 : "=r"(r[0]), "=r"(r[1]), "=r"(r[2]), "=r"(r[3]) : "r"(addr));
}
__device__ __forceinline__ void mma16816(float* d, const uint32_t* a,
                                         const uint32_t* b) {
    asm volatile("mma.sync.aligned.m16n8k16.row.col.f32.bf16.bf16.f32 "
                 "{%0,%1,%2,%3}, {%4,%5,%6,%7}, {%8,%9}, {%0,%1,%2,%3};"
                 : "+f"(d[0]), "+f"(d[1]), "+f"(d[2]), "+f"(d[3])
                 : "r"(a[0]), "r"(a[1]), "r"(a[2]), "r"(a[3]),
                   "r"(b[0]), "r"(b[1]));
}
__device__ __forceinline__ uint32_t pack_bf16(float x, float y) {
    __nv_bfloat162 p;
    p.x = __float2bfloat16(x);
    p.y = __float2bfloat16(y);
    return *(uint32_t*)&p;
}
__device__ __forceinline__ void split_lo(uint32_t hi, float x, float y,
                                         uint32_t* lo) {
    __nv_bfloat162* h = (__nv_bfloat162*)&hi;
    *lo = pack_bf16(x - __bfloat162float(h->x), y - __bfloat162float(h->y));
}

#define PADK 40

// ========== bf16x3 NT GEMM via mma.sync: C[M][N] = A[M][K] @ B[N][K]^T ======
// Block tile 128x128, K-chunk 32. 8 warps: 4(m) x 2(n), warp tile 32x64.
__global__ void __launch_bounds__(256)
gemm_mma(const float* __restrict__ A, const float* __restrict__ B,
         float* __restrict__ C, int N, int K) {
    __shared__ __align__(16) __nv_bfloat16 sAh[128 * PADK], sAl[128 * PADK],
                                           sBh[128 * PADK], sBl[128 * PADK];
    const int tid = threadIdx.x, lane = tid & 31, wid = tid >> 5;
    const int wm = wid & 3, wn = wid >> 2;
    const int bm = blockIdx.y * 128, bn = blockIdx.x * 128;

    const uint32_t sb_ah = smem_u32(sAh), sb_al = smem_u32(sAl);
    const uint32_t sb_bh = smem_u32(sBh), sb_bl = smem_u32(sBl);

    float acc[2][8][4] = {};
    float2 av[8], bv[8];

    auto load_stage = [&](int kt) {
        #pragma unroll
        for (int j = 0; j < 8; j++) {
            int idx = j * 256 + tid;
            int row = idx >> 4, c2 = idx & 15;
            av[j] = *(const float2*)&A[(size_t)(bm + row) * K + kt + c2 * 2];
            bv[j] = *(const float2*)&B[(size_t)(bn + row) * K + kt + c2 * 2];
        }
    };
    auto store_stage = [&]() {
        #pragma unroll
        for (int j = 0; j < 8; j++) {
            int idx = j * 256 + tid;
            int row = idx >> 4, c2 = idx & 15;
            int off = row * PADK + c2 * 2;
            uint32_t ah = pack_bf16(av[j].x, av[j].y);
            *(uint32_t*)&sAh[off] = ah;
            split_lo(ah, av[j].x, av[j].y, (uint32_t*)&sAl[off]);
            uint32_t bh = pack_bf16(bv[j].x, bv[j].y);
            *(uint32_t*)&sBh[off] = bh;
            split_lo(bh, bv[j].x, bv[j].y, (uint32_t*)&sBl[off]);
        }
    };

    const int nch = K / 32;
    load_stage(0);
    for (int ch = 0; ch < nch; ch++) {
        store_stage();
        __syncthreads();
        if (ch + 1 < nch) load_stage((ch + 1) * 32);

        #pragma unroll
        for (int ks = 0; ks < 2; ks++) {
            uint32_t ahf[2][4], alf[2][4];
            const int arow = wm * 32 + (lane & 15);
            const int acol = ks * 16 + (lane >> 4) * 8;
            #pragma unroll
            for (int mf = 0; mf < 2; mf++) {
                uint32_t ad = (uint32_t)(((arow + mf * 16) * PADK + acol) * 2);
                ldsm4(ahf[mf], sb_ah + ad);
                ldsm4(alf[mf], sb_al + ad);
            }
            const int brow = wn * 64 + ((lane >> 4) << 3) + (lane & 7);
            const int bcol = ks * 16 + ((lane >> 3) & 1) * 8;
            #pragma unroll
            for (int nf2 = 0; nf2 < 4; nf2++) {
                uint32_t bd = (uint32_t)(((brow + nf2 * 16) * PADK + bcol) * 2);
                uint32_t bhf[4], blf[4];
                ldsm4(bhf, sb_bh + bd);
                ldsm4(blf, sb_bl + bd);
                #pragma unroll
                for (int h = 0; h < 2; h++) {
                    #pragma unroll
                    for (int mf = 0; mf < 2; mf++) {
                        float* d = acc[mf][nf2 * 2 + h];
                        mma16816(d, ahf[mf], bhf + 2 * h);
                        mma16816(d, ahf[mf], blf + 2 * h);
                        mma16816(d, alf[mf], bhf + 2 * h);
                    }
                }
            }
        }
        __syncthreads();
    }

    #pragma unroll
    for (int mf = 0; mf < 2; mf++) {
        const int r = bm + wm * 32 + mf * 16 + (lane >> 2);
        #pragma unroll
        for (int nf = 0; nf < 8; nf++) {
            const int c = bn + wn * 64 + nf * 8 + (lane & 3) * 2;
            *(float2*)&C[(size_t)r * N + c] =
                make_float2(acc[mf][nf][0], acc[mf][nf][1]);
            *(float2*)&C[(size_t)(r + 8) * N + c] =
                make_float2(acc[mf][nf][2], acc[mf][nf][3]);
        }
    }
}

// ========== fused flash attention (S = QK^T/64, mask, arc, softmax, PV) =====
// grid (S/128 q-tiles, B*MHEAD), 256 threads. Warp w owns 16 q-rows:
// q0 + w*16 .. +15 (full k-width per warp -> no cross-warp softmax reduce).
// K-tiles 64 wide. P reused register-to-register via C-frag -> A-frag identity.
#define SQPAD 72            // Q/K rows: 64 cols + 8 pad (bf16), 144B stride
#define FO_QH 0
#define FO_QL 18432
#define FO_KH 36864
#define FO_KL 46080
#define FO_VH 55296
#define FO_VL 64512
#define FO_TOTAL 73728

__global__ void __launch_bounds__(256)
flash_att(const int* __restrict__ mask_head, const int* __restrict__ mask_child,
          float* __restrict__ arc) {
    extern __shared__ char sm[];
    const int bh = blockIdx.y, b = bh >> 4, head = bh & 15;
    const int q0 = blockIdx.x * 128;
    const int tid = threadIdx.x, lane = tid & 31, w = tid >> 5;

    __nv_bfloat16* sQh = (__nv_bfloat16*)(sm + FO_QH);
    __nv_bfloat16* sQl = (__nv_bfloat16*)(sm + FO_QL);
    __nv_bfloat16* sKh = (__nv_bfloat16*)(sm + FO_KH);
    __nv_bfloat16* sKl = (__nv_bfloat16*)(sm + FO_KL);
    __nv_bfloat16* sVh = (__nv_bfloat16*)(sm + FO_VH);
    __nv_bfloat16* sVl = (__nv_bfloat16*)(sm + FO_VL);
    const uint32_t sb_qh = smem_u32(sQh), sb_ql = smem_u32(sQl);
    const uint32_t sb_kh = smem_u32(sKh), sb_kl = smem_u32(sKl);
    const uint32_t sb_vh = smem_u32(sVh), sb_vl = smem_u32(sVl);

    const float* qbase = g_qkv + ((size_t)b * SEQ + q0) * E3 + head * HD;
    const float* kbase = g_qkv + (size_t)b * SEQ * E3 + EMB + head * HD;
    const float* vbase = g_qkv + (size_t)b * SEQ * E3 + 2 * EMB + head * HD;
    const int* msk = ((head >> 3) == 0 ? mask_head : mask_child)
                     + (size_t)b * SEQ * SEQ;
    float* arcp = arc + (size_t)bh * SEQ * SEQ;

    // ---- zero arc above-diagonal region: rows q0..q0+127, cols q0+128.. ----
    {
        const int zc4 = (SEQ - q0 - 128) >> 2;        // float4 count per row
        const float4 z4 = make_float4(0.f, 0.f, 0.f, 0.f);
        for (int i = tid; i < 128 * zc4; i += 256) {
            int r = i / (zc4 ? zc4 : 1), c = i - r * zc4;
            *(float4*)&arcp[(size_t)(q0 + r) * SEQ + q0 + 128 + c * 4] = z4;
        }
    }

    // ---- stage Q (128 x 64) hi/lo into smem ----
    #pragma unroll
    for (int j = 0; j < 16; j++) {
        int idx = j * 256 + tid;                      // 4096 float2
        int row = idx >> 5, c2 = idx & 31;
        float2 qv = *(const float2*)&qbase[(size_t)row * E3 + c2 * 2];
        int off = row * SQPAD + c2 * 2;
        uint32_t qh = pack_bf16(qv.x, qv.y);
        *(uint32_t*)&sQh[off] = qh;
        split_lo(qh, qv.x, qv.y, (uint32_t*)&sQl[off]);
    }
    __syncthreads();

    // ---- preload Q fragments (loop-invariant): 4 k-steps, hi/lo ----
    uint32_t qhf[4][4], qlf[4][4];
    {
        const int arow = w * 16 + (lane & 15);
        #pragma unroll
        for (int ks = 0; ks < 4; ks++) {
            const int acol = ks * 16 + (lane >> 4) * 8;
            uint32_t ad = (uint32_t)((arow * SQPAD + acol) * 2);
            ldsm4(qhf[ks], sb_qh + ad);
            ldsm4(qlf[ks], sb_ql + ad);
        }
    }

    // ---- online softmax state (per thread: 2 rows) + O accumulator ----
    const int r0 = lane >> 2;                // rows w*16 + r0, + r0+8
    float m[2] = {-INFINITY, -INFINITY}, l[2] = {0.f, 0.f};
    float o[8][4] = {};                      // m16 n64 output frags

    const int ntiles = (q0 + 128) / 64;      // causal: cols < q0+128
    for (int kt = 0; kt < ntiles; kt++) {
        const int k0 = kt * 64;
        // -- load K tile (64x64) hi/lo --
        #pragma unroll
        for (int j = 0; j < 8; j++) {
            int idx = j * 256 + tid;                  // 2048 float2
            int row = idx >> 5, c2 = idx & 31;
            float2 kv = *(const float2*)&kbase[(size_t)(k0 + row) * E3 + c2 * 2];
            int off = row * SQPAD + c2 * 2;
            uint32_t kh = pack_bf16(kv.x, kv.y);
            *(uint32_t*)&sKh[off] = kh;
            split_lo(kh, kv.x, kv.y, (uint32_t*)&sKl[off]);
        }
        // -- load V tile (64x64) transposed: sV[c][k] --
        #pragma unroll
        for (int j = 0; j < 4; j++) {
            int idx = j * 256 + tid;                  // 1024 float4
            int k = idx >> 4, c4 = (idx & 15) * 4;
            float4 vv = *(const float4*)&vbase[(size_t)(k0 + k) * E3 + c4];
            #pragma unroll
            for (int e = 0; e < 4; e++) {
                float f = (&vv.x)[e];
                __nv_bfloat16 h = __float2bfloat16(f);
                sVh[(c4 + e) * SQPAD + k] = h;
                sVl[(c4 + e) * SQPAD + k] =
                    __float2bfloat16(f - __bfloat162float(h));
            }
        }
        __syncthreads();

        // -- S = Q K^T (m16 x n64, bf16x3) --
        float s[8][4] = {};
        #pragma unroll
        for (int ks = 0; ks < 4; ks++) {
            const int brow = ((lane >> 4) << 3) + (lane & 7);
            const int bcol = ks * 16 + ((lane >> 3) & 1) * 8;
            #pragma unroll
            for (int nf2 = 0; nf2 < 4; nf2++) {
                uint32_t bd = (uint32_t)(((nf2 * 16 + brow) * SQPAD + bcol) * 2);
                uint32_t bhf[4], blf[4];
                ldsm4(bhf, sb_kh + bd);
                ldsm4(blf, sb_kl + bd);
                #pragma unroll
                for (int h = 0; h < 2; h++) {
                    float* d = s[nf2 * 2 + h];
                    mma16816(d, qhf[ks], bhf + 2 * h);
                    mma16816(d, qhf[ks], blf + 2 * h);
                    mma16816(d, qlf[ks], bhf + 2 * h);
                }
            }
        }

        // -- epilogue: scale, causal+mask, arc=sigmoid, s=val|-inf --
        #pragma unroll
        for (int half = 0; half < 2; half++) {
            const int qi = q0 + w * 16 + r0 + half * 8;
            #pragma unroll
            for (int nf = 0; nf < 8; nf++) {
                const int kj = k0 + nf * 8 + (lane & 3) * 2;
                const size_t idx = (size_t)qi * SEQ + kj;
                const int2 mv = *(const int2*)&msk[idx];
                float2 og;
                #pragma unroll
                for (int e = 0; e < 2; e++) {
                    float val = s[nf][half * 2 + e] * (1.0f / 64.0f);
                    bool valid = (kj + e <= qi) && ((e ? mv.y : mv.x) != 0);
                    s[nf][half * 2 + e] = valid ? val : -INFINITY;
                    (&og.x)[e] = valid ? 1.0f / (1.0f + __expf(-val)) : 0.0f;
                }
                *(float2*)&arcp[idx] = og;
            }
        }

        // -- online softmax update --
        float alpha[2];
        #pragma unroll
        for (int i = 0; i < 2; i++) {
            float tmax = -INFINITY;
            #pragma unroll
            for (int nf = 0; nf < 8; nf++)
                tmax = fmaxf(tmax, fmaxf(s[nf][i * 2], s[nf][i * 2 + 1]));
            tmax = fmaxf(tmax, __shfl_xor_sync(0xffffffffu, tmax, 1));
            tmax = fmaxf(tmax, __shfl_xor_sync(0xffffffffu, tmax, 2));
            float mnew = fmaxf(m[i], tmax);
            alpha[i] = (m[i] == -INFINITY) ? 0.0f : __expf(m[i] - mnew);
            float tsum = 0.0f;
            #pragma unroll
            for (int nf = 0; nf < 8; nf++) {
                #pragma unroll
                for (int e = 0; e < 2; e++) {
                    float p = (mnew == -INFINITY)
                              ? 0.0f : __expf(s[nf][i * 2 + e] - mnew);
                    s[nf][i * 2 + e] = p;
                    tsum += p;
                }
            }
            tsum += __shfl_xor_sync(0xffffffffu, tsum, 1);
            tsum += __shfl_xor_sync(0xffffffffu, tsum, 2);
            l[i] = l[i] * alpha[i] + tsum;
            m[i] = mnew;
        }
        #pragma unroll
        for (int nf = 0; nf < 8; nf++) {
            o[nf][0] *= alpha[0]; o[nf][1] *= alpha[0];
            o[nf][2] *= alpha[1]; o[nf][3] *= alpha[1];
        }

        // -- P fragments (C-frag -> A-frag identity), hi/lo --
        uint32_t ph[4][4], pl[4][4];
        #pragma unroll
        for (int j = 0; j < 4; j++) {
            const float* e0 = s[2 * j];      // k = j*16 + (lane&3)*2 (+1)
            const float* e1 = s[2 * j + 1];  // k = +8
            ph[j][0] = pack_bf16(e0[0], e0[1]);
            split_lo(ph[j][0], e0[0], e0[1], &pl[j][0]);
            ph[j][1] = pack_bf16(e0[2], e0[3]);
            split_lo(ph[j][1], e0[2], e0[3], &pl[j][1]);
            ph[j][2] = pack_bf16(e1[0], e1[1]);
            split_lo(ph[j][2], e1[0], e1[1], &pl[j][2]);
            ph[j][3] = pack_bf16(e1[2], e1[3]);
            split_lo(ph[j][3], e1[2], e1[3], &pl[j][3]);
        }

        // -- O += P V  (m16 n64 k64, bf16x3) --
        #pragma unroll
        for (int j = 0; j < 4; j++) {        // k-steps over P's 64 keys
            const int brow = ((lane >> 4) << 3) + (lane & 7);
            const int bcol = j * 16 + ((lane >> 3) & 1) * 8;
            #pragma unroll
            for (int nf2 = 0; nf2 < 4; nf2++) {
                uint32_t bd = (uint32_t)(((nf2 * 16 + brow) * SQPAD + bcol) * 2);
                uint32_t bhf[4], blf[4];
                ldsm4(bhf, sb_vh + bd);
                ldsm4(blf, sb_vl + bd);
                #pragma unroll
                for (int h = 0; h < 2; h++) {
                    float* d = o[nf2 * 2 + h];
                    mma16816(d, ph[j], bhf + 2 * h);
                    mma16816(d, ph[j], blf + 2 * h);
                    mma16816(d, pl[j], bhf + 2 * h);
                }
            }
        }
        __syncthreads();
    }

    // ---- normalize and write O ----
    const float inv0 = (l[0] > 0.f) ? 1.0f / l[0] : 0.0f;
    const float inv1 = (l[1] > 0.f) ? 1.0f / l[1] : 0.0f;
    const int r = q0 + w * 16 + r0;
    #pragma unroll
    for (int nf = 0; nf < 8; nf++) {
        const int c = head * HD + nf * 8 + (lane & 3) * 2;
        *(float2*)&g_ao[(size_t)(b * SEQ + r) * EMB + c] =
            make_float2(o[nf][0] * inv0, o[nf][1] * inv0);
        *(float2*)&g_ao[(size_t)(b * SEQ + r + 8) * EMB + c] =
            make_float2(o[nf][2] * inv1, o[nf][3] * inv1);
    }
}

// ---------------- launch ----------------------------------------------------
extern "C" void kernel_launch(void* const* d_in, const int* in_sizes, int n_in,
                              void* d_out, int out_size) {
    const float* x      = (const float*)d_in[0];
    const float* w_qkv  = (const float*)d_in[1];
    const float* w_proj = (const float*)d_in[2];
    const int*   m_head  = (const int*)d_in[3];
    const int*   m_child = (const int*)d_in[4];

    float* out = (float*)d_out;
    float* arc = out + (size_t)BATCH * SEQ * EMB;

    float *p_qkv, *p_ao;
    cudaGetSymbolAddress((void**)&p_qkv, g_qkv);
    cudaGetSymbolAddress((void**)&p_ao,  g_ao);

    cudaFuncSetAttribute(flash_att,
                         cudaFuncAttributeMaxDynamicSharedMemorySize, FO_TOTAL);

    // 1) QKV = X @ Wqkv^T : [2048,3072]  (bf16x3 mma.sync)
    gemm_mma<<<dim3(E3 / 128, BATCH * SEQ / 128), 256>>>(
        x, w_qkv, p_qkv, E3, EMB);

    // 2) fused: scores + mask + sigmoid(arc) + online softmax + P@V
    flash_att<<<dim3(SEQ / 128, BATCH * MHEAD), 256, FO_TOTAL>>>(
        m_head, m_child, arc);

    // 3) out = AO @ Wproj^T  (bf16x3 mma.sync)
    gemm_mma<<<dim3(EMB / 128, BATCH * SEQ / 128), 256>>>(
        p_ao, w_proj, out, EMB, EMB);
}

// round 8
// speedup vs baseline: 1.1132x; 1.0204x over previous
#include <cuda_runtime.h>
#include <cuda_bf16.h>
#include <math.h>
#include <stdint.h>

#define SEQ   1024
#define EMB   1024
#define BATCH 2
#define MHEAD 16      // total heads (M*H)
#define HD    64      // head dim
#define E3    (3*EMB)

// ---------------- scratch (allocation-free rule: __device__ globals) --------
__device__ float g_qkv[(size_t)BATCH*SEQ*E3];   // [2048][3072]  q|k|v
__device__ float g_ao [(size_t)BATCH*SEQ*EMB];  // attention out pre-proj

// ===================== helpers ==============================================
__device__ __forceinline__ uint32_t smem_u32(const void* p) {
    uint32_t a;
    asm("{ .reg .u64 t; cvta.to.shared.u64 t, %1; cvt.u32.u64 %0, t; }"
        : "=r"(a) : "l"(p));
    return a;
}
__device__ __forceinline__ void ldsm4(uint32_t* r, uint32_t addr) {
    asm volatile("ldmatrix.sync.aligned.m8n8.x4.shared.b16 {%0,%1,%2,%3}, [%4];"
                 : "=r"(r[0]), "=r"(r[1]), "=r"(r[2]), "=r"(r[3]) : "r"(addr));
}
__device__ __forceinline__ void mma16816(float* d, const uint32_t* a,
                                         const uint32_t* b) {
    asm volatile("mma.sync.aligned.m16n8k16.row.col.f32.bf16.bf16.f32 "
                 "{%0,%1,%2,%3}, {%4,%5,%6,%7}, {%8,%9}, {%0,%1,%2,%3};"
                 : "+f"(d[0]), "+f"(d[1]), "+f"(d[2]), "+f"(d[3])
                 : "r"(a[0]), "r"(a[1]), "r"(a[2]), "r"(a[3]),
                   "r"(b[0]), "r"(b[1]));
}
__device__ __forceinline__ uint32_t pack_bf16(float x, float y) {
    __nv_bfloat162 p;
    p.x = __float2bfloat16(x);
    p.y = __float2bfloat16(y);
    return *(uint32_t*)&p;
}
__device__ __forceinline__ void split_lo(uint32_t hi, float x, float y,
                                         uint32_t* lo) {
    __nv_bfloat162* h = (__nv_bfloat162*)&hi;
    *lo = pack_bf16(x - __bfloat162float(h->x), y - __bfloat162float(h->y));
}

#define PADK 40

// ========== bf16x3 NT GEMM via mma.sync: C[M][N] = A[M][K] @ B[N][K]^T ======
// Block tile 128x128, K-chunk 32. 8 warps: 4(m) x 2(n), warp tile 32x64.
__global__ void __launch_bounds__(256)
gemm_mma(const float* __restrict__ A, const float* __restrict__ B,
         float* __restrict__ C, int N, int K) {
    __shared__ __align__(16) __nv_bfloat16 sAh[128 * PADK], sAl[128 * PADK],
                                           sBh[128 * PADK], sBl[128 * PADK];
    const int tid = threadIdx.x, lane = tid & 31, wid = tid >> 5;
    const int wm = wid & 3, wn = wid >> 2;
    const int bm = blockIdx.y * 128, bn = blockIdx.x * 128;

    const uint32_t sb_ah = smem_u32(sAh), sb_al = smem_u32(sAl);
    const uint32_t sb_bh = smem_u32(sBh), sb_bl = smem_u32(sBl);

    float acc[2][8][4] = {};
    float2 av[8], bv[8];

    auto load_stage = [&](int kt) {
        #pragma unroll
        for (int j = 0; j < 8; j++) {
            int idx = j * 256 + tid;
            int row = idx >> 4, c2 = idx & 15;
            av[j] = *(const float2*)&A[(size_t)(bm + row) * K + kt + c2 * 2];
            bv[j] = *(const float2*)&B[(size_t)(bn + row) * K + kt + c2 * 2];
        }
    };
    auto store_stage = [&]() {
        #pragma unroll
        for (int j = 0; j < 8; j++) {
            int idx = j * 256 + tid;
            int row = idx >> 4, c2 = idx & 15;
            int off = row * PADK + c2 * 2;
            uint32_t ah = pack_bf16(av[j].x, av[j].y);
            *(uint32_t*)&sAh[off] = ah;
            split_lo(ah, av[j].x, av[j].y, (uint32_t*)&sAl[off]);
            uint32_t bh = pack_bf16(bv[j].x, bv[j].y);
            *(uint32_t*)&sBh[off] = bh;
            split_lo(bh, bv[j].x, bv[j].y, (uint32_t*)&sBl[off]);
        }
    };

    const int nch = K / 32;
    load_stage(0);
    for (int ch = 0; ch < nch; ch++) {
        store_stage();
        __syncthreads();
        if (ch + 1 < nch) load_stage((ch + 1) * 32);

        #pragma unroll
        for (int ks = 0; ks < 2; ks++) {
            uint32_t ahf[2][4], alf[2][4];
            const int arow = wm * 32 + (lane & 15);
            const int acol = ks * 16 + (lane >> 4) * 8;
            #pragma unroll
            for (int mf = 0; mf < 2; mf++) {
                uint32_t ad = (uint32_t)(((arow + mf * 16) * PADK + acol) * 2);
                ldsm4(ahf[mf], sb_ah + ad);
                ldsm4(alf[mf], sb_al + ad);
            }
            const int brow = wn * 64 + ((lane >> 4) << 3) + (lane & 7);
            const int bcol = ks * 16 + ((lane >> 3) & 1) * 8;
            #pragma unroll
            for (int nf2 = 0; nf2 < 4; nf2++) {
                uint32_t bd = (uint32_t)(((brow + nf2 * 16) * PADK + bcol) * 2);
                uint32_t bhf[4], blf[4];
                ldsm4(bhf, sb_bh + bd);
                ldsm4(blf, sb_bl + bd);
                #pragma unroll
                for (int h = 0; h < 2; h++) {
                    #pragma unroll
                    for (int mf = 0; mf < 2; mf++) {
                        float* d = acc[mf][nf2 * 2 + h];
                        mma16816(d, ahf[mf], bhf + 2 * h);
                        mma16816(d, ahf[mf], blf + 2 * h);
                        mma16816(d, alf[mf], bhf + 2 * h);
                    }
                }
            }
        }
        __syncthreads();
    }

    #pragma unroll
    for (int mf = 0; mf < 2; mf++) {
        const int r = bm + wm * 32 + mf * 16 + (lane >> 2);
        #pragma unroll
        for (int nf = 0; nf < 8; nf++) {
            const int c = bn + wn * 64 + nf * 8 + (lane & 3) * 2;
            *(float2*)&C[(size_t)r * N + c] =
                make_float2(acc[mf][nf][0], acc[mf][nf][1]);
            *(float2*)&C[(size_t)(r + 8) * N + c] =
                make_float2(acc[mf][nf][2], acc[mf][nf][3]);
        }
    }
}

// ========== fused flash attention (S = QK^T/64, mask, arc, softmax, PV) =====
// grid (S/128 q-tiles, B*MHEAD), 256 threads. Warp w owns 16 q-rows.
// K-tiles 64 wide; next tile prefetched to registers during compute.
// Heavy q-tiles scheduled first (work ~ q0).
#define SQPAD 72            // rows: 64 cols + 8 pad (bf16), 144B stride
#define FO_QH 0
#define FO_QL 18432
#define FO_KH 36864
#define FO_KL 46080
#define FO_VH 55296
#define FO_VL 64512
#define FO_TOTAL 73728

__global__ void __launch_bounds__(256)
flash_att(const int* __restrict__ mask_head, const int* __restrict__ mask_child,
          float* __restrict__ arc) {
    extern __shared__ char sm[];
    const int bh = blockIdx.y, b = bh >> 4, head = bh & 15;
    const int q0 = (int)(gridDim.x - 1 - blockIdx.x) * 128;  // heavy first
    const int tid = threadIdx.x, lane = tid & 31, w = tid >> 5;

    __nv_bfloat16* sQh = (__nv_bfloat16*)(sm + FO_QH);
    __nv_bfloat16* sQl = (__nv_bfloat16*)(sm + FO_QL);
    __nv_bfloat16* sKh = (__nv_bfloat16*)(sm + FO_KH);
    __nv_bfloat16* sKl = (__nv_bfloat16*)(sm + FO_KL);
    __nv_bfloat16* sVh = (__nv_bfloat16*)(sm + FO_VH);
    __nv_bfloat16* sVl = (__nv_bfloat16*)(sm + FO_VL);
    const uint32_t sb_qh = smem_u32(sQh), sb_ql = smem_u32(sQl);
    const uint32_t sb_kh = smem_u32(sKh), sb_kl = smem_u32(sKl);
    const uint32_t sb_vh = smem_u32(sVh), sb_vl = smem_u32(sVl);

    const float* qbase = g_qkv + ((size_t)b * SEQ + q0) * E3 + head * HD;
    const float* kbase = g_qkv + (size_t)b * SEQ * E3 + EMB + head * HD;
    const float* vbase = g_qkv + (size_t)b * SEQ * E3 + 2 * EMB + head * HD;
    const int* msk = ((head >> 3) == 0 ? mask_head : mask_child)
                     + (size_t)b * SEQ * SEQ;
    float* arcp = arc + (size_t)bh * SEQ * SEQ;

    // ---- zero arc above-diagonal region: rows q0..q0+127, cols q0+128.. ----
    {
        const int zc4 = (SEQ - q0 - 128) >> 2;        // float4 count per row
        const float4 z4 = make_float4(0.f, 0.f, 0.f, 0.f);
        for (int i = tid; i < 128 * zc4; i += 256) {
            int r = i / (zc4 ? zc4 : 1), c = i - r * zc4;
            *(float4*)&arcp[(size_t)(q0 + r) * SEQ + q0 + 128 + c * 4] = z4;
        }
    }

    // ---- stage Q (128 x 64) hi/lo into smem ----
    #pragma unroll
    for (int j = 0; j < 16; j++) {
        int idx = j * 256 + tid;                      // 4096 float2
        int row = idx >> 5, c2 = idx & 31;
        float2 qv = *(const float2*)&qbase[(size_t)row * E3 + c2 * 2];
        int off = row * SQPAD + c2 * 2;
        uint32_t qh = pack_bf16(qv.x, qv.y);
        *(uint32_t*)&sQh[off] = qh;
        split_lo(qh, qv.x, qv.y, (uint32_t*)&sQl[off]);
    }
    __syncthreads();

    // ---- preload Q fragments (loop-invariant): 4 k-steps, hi/lo ----
    uint32_t qhf[4][4], qlf[4][4];
    {
        const int arow = w * 16 + (lane & 15);
        #pragma unroll
        for (int ks = 0; ks < 4; ks++) {
            const int acol = ks * 16 + (lane >> 4) * 8;
            uint32_t ad = (uint32_t)((arow * SQPAD + acol) * 2);
            ldsm4(qhf[ks], sb_qh + ad);
            ldsm4(qlf[ks], sb_ql + ad);
        }
    }

    // ---- K/V tile staging (register prefetch) ----
    float2 kreg[8];
    float4 vreg[4];
    auto load_kv = [&](int k0) {
        #pragma unroll
        for (int j = 0; j < 8; j++) {
            int idx = j * 256 + tid;                  // 2048 float2
            int row = idx >> 5, c2 = idx & 31;
            kreg[j] = *(const float2*)&kbase[(size_t)(k0 + row) * E3 + c2 * 2];
        }
        #pragma unroll
        for (int j = 0; j < 4; j++) {
            int idx = j * 256 + tid;                  // 1024 float4
            int k = idx >> 4, c4 = (idx & 15) * 4;
            vreg[j] = *(const float4*)&vbase[(size_t)(k0 + k) * E3 + c4];
        }
    };
    auto store_kv = [&]() {
        #pragma unroll
        for (int j = 0; j < 8; j++) {
            int idx = j * 256 + tid;
            int row = idx >> 5, c2 = idx & 31;
            int off = row * SQPAD + c2 * 2;
            uint32_t kh = pack_bf16(kreg[j].x, kreg[j].y);
            *(uint32_t*)&sKh[off] = kh;
            split_lo(kh, kreg[j].x, kreg[j].y, (uint32_t*)&sKl[off]);
        }
        #pragma unroll
        for (int j = 0; j < 4; j++) {
            int idx = j * 256 + tid;
            int k = idx >> 4, c4 = (idx & 15) * 4;
            #pragma unroll
            for (int e = 0; e < 4; e++) {
                float f = (&vreg[j].x)[e];
                __nv_bfloat16 h = __float2bfloat16(f);
                sVh[(c4 + e) * SQPAD + k] = h;
                sVl[(c4 + e) * SQPAD + k] =
                    __float2bfloat16(f - __bfloat162float(h));
            }
        }
    };

    // ---- online softmax state (per thread: 2 rows) + O accumulator ----
    const int r0 = lane >> 2;                // rows w*16 + r0, + r0+8
    float m[2] = {-INFINITY, -INFINITY}, l[2] = {0.f, 0.f};
    float o[8][4] = {};                      // m16 n64 output frags

    const int ntiles = (q0 + 128) / 64;      // causal: cols < q0+128
    load_kv(0);
    for (int kt = 0; kt < ntiles; kt++) {
        const int k0 = kt * 64;
        store_kv();
        __syncthreads();
        if (kt + 1 < ntiles) load_kv((kt + 1) * 64);  // prefetch next tile

        // -- S = Q K^T (m16 x n64, bf16x3) --
        float s[8][4] = {};
        #pragma unroll
        for (int ks = 0; ks < 4; ks++) {
            const int brow = ((lane >> 4) << 3) + (lane & 7);
            const int bcol = ks * 16 + ((lane >> 3) & 1) * 8;
            #pragma unroll
            for (int nf2 = 0; nf2 < 4; nf2++) {
                uint32_t bd = (uint32_t)(((nf2 * 16 + brow) * SQPAD + bcol) * 2);
                uint32_t bhf[4], blf[4];
                ldsm4(bhf, sb_kh + bd);
                ldsm4(blf, sb_kl + bd);
                #pragma unroll
                for (int h = 0; h < 2; h++) {
                    float* d = s[nf2 * 2 + h];
                    mma16816(d, qhf[ks], bhf + 2 * h);
                    mma16816(d, qhf[ks], blf + 2 * h);
                    mma16816(d, qlf[ks], bhf + 2 * h);
                }
            }
        }

        // -- epilogue: scale, causal+mask, arc=sigmoid, s=val|-inf --
        #pragma unroll
        for (int half = 0; half < 2; half++) {
            const int qi = q0 + w * 16 + r0 + half * 8;
            #pragma unroll
            for (int nf = 0; nf < 8; nf++) {
                const int kj = k0 + nf * 8 + (lane & 3) * 2;
                const size_t idx = (size_t)qi * SEQ + kj;
                const int2 mv = *(const int2*)&msk[idx];
                float2 og;
                #pragma unroll
                for (int e = 0; e < 2; e++) {
                    float val = s[nf][half * 2 + e] * (1.0f / 64.0f);
                    bool valid = (kj + e <= qi) && ((e ? mv.y : mv.x) != 0);
                    s[nf][half * 2 + e] = valid ? val : -INFINITY;
                    (&og.x)[e] = valid ? 1.0f / (1.0f + __expf(-val)) : 0.0f;
                }
                *(float2*)&arcp[idx] = og;
            }
        }

        // -- online softmax update --
        float alpha[2];
        #pragma unroll
        for (int i = 0; i < 2; i++) {
            float tmax = -INFINITY;
            #pragma unroll
            for (int nf = 0; nf < 8; nf++)
                tmax = fmaxf(tmax, fmaxf(s[nf][i * 2], s[nf][i * 2 + 1]));
            tmax = fmaxf(tmax, __shfl_xor_sync(0xffffffffu, tmax, 1));
            tmax = fmaxf(tmax, __shfl_xor_sync(0xffffffffu, tmax, 2));
            float mnew = fmaxf(m[i], tmax);
            alpha[i] = (m[i] == -INFINITY) ? 0.0f : __expf(m[i] - mnew);
            float tsum = 0.0f;
            #pragma unroll
            for (int nf = 0; nf < 8; nf++) {
                #pragma unroll
                for (int e = 0; e < 2; e++) {
                    float p = (mnew == -INFINITY)
                              ? 0.0f : __expf(s[nf][i * 2 + e] - mnew);
                    s[nf][i * 2 + e] = p;
                    tsum += p;
                }
            }
            tsum += __shfl_xor_sync(0xffffffffu, tsum, 1);
            tsum += __shfl_xor_sync(0xffffffffu, tsum, 2);
            l[i] = l[i] * alpha[i] + tsum;
            m[i] = mnew;
        }
        #pragma unroll
        for (int nf = 0; nf < 8; nf++) {
            o[nf][0] *= alpha[0]; o[nf][1] *= alpha[0];
            o[nf][2] *= alpha[1]; o[nf][3] *= alpha[1];
        }

        // -- P fragments (C-frag -> A-frag identity), hi/lo --
        uint32_t ph[4][4], pl[4][4];
        #pragma unroll
        for (int j = 0; j < 4; j++) {
            const float* e0 = s[2 * j];      // k = j*16 + (lane&3)*2 (+1)
            const float* e1 = s[2 * j + 1];  // k = +8
            ph[j][0] = pack_bf16(e0[0], e0[1]);
            split_lo(ph[j][0], e0[0], e0[1], &pl[j][0]);
            ph[j][1] = pack_bf16(e0[2], e0[3]);
            split_lo(ph[j][1], e0[2], e0[3], &pl[j][1]);
            ph[j][2] = pack_bf16(e1[0], e1[1]);
            split_lo(ph[j][2], e1[0], e1[1], &pl[j][2]);
            ph[j][3] = pack_bf16(e1[2], e1[3]);
            split_lo(ph[j][3], e1[2], e1[3], &pl[j][3]);
        }

        // -- O += P V  (m16 n64 k64, bf16x3) --
        #pragma unroll
        for (int j = 0; j < 4; j++) {        // k-steps over P's 64 keys
            const int brow = ((lane >> 4) << 3) + (lane & 7);
            const int bcol = j * 16 + ((lane >> 3) & 1) * 8;
            #pragma unroll
            for (int nf2 = 0; nf2 < 4; nf2++) {
                uint32_t bd = (uint32_t)(((nf2 * 16 + brow) * SQPAD + bcol) * 2);
                uint32_t bhf[4], blf[4];
                ldsm4(bhf, sb_vh + bd);
                ldsm4(blf, sb_vl + bd);
                #pragma unroll
                for (int h = 0; h < 2; h++) {
                    float* d = o[nf2 * 2 + h];
                    mma16816(d, ph[j], bhf + 2 * h);
                    mma16816(d, ph[j], blf + 2 * h);
                    mma16816(d, pl[j], bhf + 2 * h);
                }
            }
        }
        __syncthreads();
    }

    // ---- normalize and write O ----
    const float inv0 = (l[0] > 0.f) ? 1.0f / l[0] : 0.0f;
    const float inv1 = (l[1] > 0.f) ? 1.0f / l[1] : 0.0f;
    const int r = q0 + w * 16 + r0;
    #pragma unroll
    for (int nf = 0; nf < 8; nf++) {
        const int c = head * HD + nf * 8 + (lane & 3) * 2;
        *(float2*)&g_ao[(size_t)(b * SEQ + r) * EMB + c] =
            make_float2(o[nf][0] * inv0, o[nf][1] * inv0);
        *(float2*)&g_ao[(size_t)(b * SEQ + r + 8) * EMB + c] =
            make_float2(o[nf][2] * inv1, o[nf][3] * inv1);
    }
}

// ---------------- launch ----------------------------------------------------
extern "C" void kernel_launch(void* const* d_in, const int* in_sizes, int n_in,
                              void* d_out, int out_size) {
    const float* x      = (const float*)d_in[0];
    const float* w_qkv  = (const float*)d_in[1];
    const float* w_proj = (const float*)d_in[2];
    const int*   m_head  = (const int*)d_in[3];
    const int*   m_child = (const int*)d_in[4];

    float* out = (float*)d_out;
    float* arc = out + (size_t)BATCH * SEQ * EMB;

    float *p_qkv, *p_ao;
    cudaGetSymbolAddress((void**)&p_qkv, g_qkv);
    cudaGetSymbolAddress((void**)&p_ao,  g_ao);

    cudaFuncSetAttribute(flash_att,
                         cudaFuncAttributeMaxDynamicSharedMemorySize, FO_TOTAL);

    // 1) QKV = X @ Wqkv^T : [2048,3072]  (bf16x3 mma.sync)
    gemm_mma<<<dim3(E3 / 128, BATCH * SEQ / 128), 256>>>(
        x, w_qkv, p_qkv, E3, EMB);

    // 2) fused: scores + mask + sigmoid(arc) + online softmax + P@V
    flash_att<<<dim3(SEQ / 128, BATCH * MHEAD), 256, FO_TOTAL>>>(
        m_head, m_child, arc);

    // 3) out = AO @ Wproj^T  (bf16x3 mma.sync)
    gemm_mma<<<dim3(EMB / 128, BATCH * SEQ / 128), 256>>>(
        p_ao, w_proj, out, EMB, EMB);
}

// round 9
// speedup vs baseline: 1.2634x; 1.1349x over previous
#include <cuda_runtime.h>
#include <cuda_bf16.h>
#include <math.h>
#include <stdint.h>

#define SEQ   1024
#define EMB   1024
#define BATCH 2
#define MHEAD 16      // total heads (M*H)
#define HD    64      // head dim
#define E3    (3*EMB)

// ---------------- scratch (allocation-free rule: __device__ globals) --------
__device__ float g_qkv[(size_t)BATCH*SEQ*E3];   // [2048][3072]  q|k|v
__device__ float g_ao [(size_t)BATCH*SEQ*EMB];  // attention out pre-proj

// ===================== helpers ==============================================
__device__ __forceinline__ uint32_t smem_u32(const void* p) {
    uint32_t a;
    asm("{ .reg .u64 t; cvta.to.shared.u64 t, %1; cvt.u32.u64 %0, t; }"
        : "=r"(a) : "l"(p));
    return a;
}
__device__ __forceinline__ void ldsm4(uint32_t* r, uint32_t addr) {
    asm volatile("ldmatrix.sync.aligned.m8n8.x4.shared.b16 {%0,%1,%2,%3}, [%4];"
                 : "=r"(r[0]), "=r"(r[1]), "=r"(r[2]), "=r"(r[3]) : "r"(addr));
}
__device__ __forceinline__ void mma16816(float* d, const uint32_t* a,
                                         const uint32_t* b) {
    asm volatile("mma.sync.aligned.m16n8k16.row.col.f32.bf16.bf16.f32 "
                 "{%0,%1,%2,%3}, {%4,%5,%6,%7}, {%8,%9}, {%0,%1,%2,%3};"
                 : "+f"(d[0]), "+f"(d[1]), "+f"(d[2]), "+f"(d[3])
                 : "r"(a[0]), "r"(a[1]), "r"(a[2]), "r"(a[3]),
                   "r"(b[0]), "r"(b[1]));
}
__device__ __forceinline__ uint32_t pack_bf16(float x, float y) {
    __nv_bfloat162 p;
    p.x = __float2bfloat16(x);
    p.y = __float2bfloat16(y);
    return *(uint32_t*)&p;
}
__device__ __forceinline__ void split_lo(uint32_t hi, float x, float y,
                                         uint32_t* lo) {
    __nv_bfloat162* h = (__nv_bfloat162*)&hi;
    *lo = pack_bf16(x - __bfloat162float(h->x), y - __bfloat162float(h->y));
}

#define PADK 40

// ========== bf16x3 NT GEMM via mma.sync: C[M][N] = A[M][K] @ B[N][K]^T ======
// Block tile 128x128, K-chunk 32. 8 warps: 4(m) x 2(n), warp tile 32x64.
__global__ void __launch_bounds__(256)
gemm_mma(const float* __restrict__ A, const float* __restrict__ B,
         float* __restrict__ C, int N, int K) {
    __shared__ __align__(16) __nv_bfloat16 sAh[128 * PADK], sAl[128 * PADK],
                                           sBh[128 * PADK], sBl[128 * PADK];
    const int tid = threadIdx.x, lane = tid & 31, wid = tid >> 5;
    const int wm = wid & 3, wn = wid >> 2;
    const int bm = blockIdx.y * 128, bn = blockIdx.x * 128;

    const uint32_t sb_ah = smem_u32(sAh), sb_al = smem_u32(sAl);
    const uint32_t sb_bh = smem_u32(sBh), sb_bl = smem_u32(sBl);

    float acc[2][8][4] = {};
    float2 av[8], bv[8];

    auto load_stage = [&](int kt) {
        #pragma unroll
        for (int j = 0; j < 8; j++) {
            int idx = j * 256 + tid;
            int row = idx >> 4, c2 = idx & 15;
            av[j] = *(const float2*)&A[(size_t)(bm + row) * K + kt + c2 * 2];
            bv[j] = *(const float2*)&B[(size_t)(bn + row) * K + kt + c2 * 2];
        }
    };
    auto store_stage = [&]() {
        #pragma unroll
        for (int j = 0; j < 8; j++) {
            int idx = j * 256 + tid;
            int row = idx >> 4, c2 = idx & 15;
            int off = row * PADK + c2 * 2;
            uint32_t ah = pack_bf16(av[j].x, av[j].y);
            *(uint32_t*)&sAh[off] = ah;
            split_lo(ah, av[j].x, av[j].y, (uint32_t*)&sAl[off]);
            uint32_t bh = pack_bf16(bv[j].x, bv[j].y);
            *(uint32_t*)&sBh[off] = bh;
            split_lo(bh, bv[j].x, bv[j].y, (uint32_t*)&sBl[off]);
        }
    };

    const int nch = K / 32;
    load_stage(0);
    for (int ch = 0; ch < nch; ch++) {
        store_stage();
        __syncthreads();
        if (ch + 1 < nch) load_stage((ch + 1) * 32);

        #pragma unroll
        for (int ks = 0; ks < 2; ks++) {
            uint32_t ahf[2][4], alf[2][4];
            const int arow = wm * 32 + (lane & 15);
            const int acol = ks * 16 + (lane >> 4) * 8;
            #pragma unroll
            for (int mf = 0; mf < 2; mf++) {
                uint32_t ad = (uint32_t)(((arow + mf * 16) * PADK + acol) * 2);
                ldsm4(ahf[mf], sb_ah + ad);
                ldsm4(alf[mf], sb_al + ad);
            }
            const int brow = wn * 64 + ((lane >> 4) << 3) + (lane & 7);
            const int bcol = ks * 16 + ((lane >> 3) & 1) * 8;
            #pragma unroll
            for (int nf2 = 0; nf2 < 4; nf2++) {
                uint32_t bd = (uint32_t)(((brow + nf2 * 16) * PADK + bcol) * 2);
                uint32_t bhf[4], blf[4];
                ldsm4(bhf, sb_bh + bd);
                ldsm4(blf, sb_bl + bd);
                #pragma unroll
                for (int h = 0; h < 2; h++) {
                    #pragma unroll
                    for (int mf = 0; mf < 2; mf++) {
                        float* d = acc[mf][nf2 * 2 + h];
                        mma16816(d, ahf[mf], bhf + 2 * h);
                        mma16816(d, ahf[mf], blf + 2 * h);
                        mma16816(d, alf[mf], bhf + 2 * h);
                    }
                }
            }
        }
        __syncthreads();
    }

    #pragma unroll
    for (int mf = 0; mf < 2; mf++) {
        const int r = bm + wm * 32 + mf * 16 + (lane >> 2);
        #pragma unroll
        for (int nf = 0; nf < 8; nf++) {
            const int c = bn + wn * 64 + nf * 8 + (lane & 3) * 2;
            *(float2*)&C[(size_t)r * N + c] =
                make_float2(acc[mf][nf][0], acc[mf][nf][1]);
            *(float2*)&C[(size_t)(r + 8) * N + c] =
                make_float2(acc[mf][nf][2], acc[mf][nf][3]);
        }
    }
}

// ========== fused flash attention (S = QK^T/64, mask, arc, softmax, PV) =====
// grid (S/64 q-tiles, B*MHEAD), 128 threads (4 warps x 16 q-rows).
// Small CTA -> 3 CTAs/SM; cross-CTA overlap hides barrier/memory stalls.
#define SQPAD 72            // rows: 64 cols + 8 pad (bf16), 144B stride
#define FO_QH 0
#define FO_QL 9216
#define FO_KH 18432
#define FO_KL 27648
#define FO_VH 36864
#define FO_VL 46080
#define FO_TOTAL 55296

__global__ void __launch_bounds__(128, 3)
flash_att(const int* __restrict__ mask_head, const int* __restrict__ mask_child,
          float* __restrict__ arc) {
    extern __shared__ char sm[];
    const int bh = blockIdx.y, b = bh >> 4, head = bh & 15;
    const int q0 = (int)(gridDim.x - 1 - blockIdx.x) * 64;   // heavy first
    const int tid = threadIdx.x, lane = tid & 31, w = tid >> 5;

    __nv_bfloat16* sQh = (__nv_bfloat16*)(sm + FO_QH);
    __nv_bfloat16* sQl = (__nv_bfloat16*)(sm + FO_QL);
    __nv_bfloat16* sKh = (__nv_bfloat16*)(sm + FO_KH);
    __nv_bfloat16* sKl = (__nv_bfloat16*)(sm + FO_KL);
    __nv_bfloat16* sVh = (__nv_bfloat16*)(sm + FO_VH);
    __nv_bfloat16* sVl = (__nv_bfloat16*)(sm + FO_VL);
    const uint32_t sb_qh = smem_u32(sQh), sb_ql = smem_u32(sQl);
    const uint32_t sb_kh = smem_u32(sKh), sb_kl = smem_u32(sKl);
    const uint32_t sb_vh = smem_u32(sVh), sb_vl = smem_u32(sVl);

    const float* qbase = g_qkv + ((size_t)b * SEQ + q0) * E3 + head * HD;
    const float* kbase = g_qkv + (size_t)b * SEQ * E3 + EMB + head * HD;
    const float* vbase = g_qkv + (size_t)b * SEQ * E3 + 2 * EMB + head * HD;
    const int* msk = ((head >> 3) == 0 ? mask_head : mask_child)
                     + (size_t)b * SEQ * SEQ;
    float* arcp = arc + (size_t)bh * SEQ * SEQ;

    // ---- zero arc above-diagonal region: rows q0..q0+63, cols q0+64.. ----
    {
        const int zc4 = (SEQ - q0 - 64) >> 2;         // float4 per row
        const float4 z4 = make_float4(0.f, 0.f, 0.f, 0.f);
        for (int i = tid; i < 64 * zc4; i += 128) {
            int r = i / (zc4 ? zc4 : 1), c = i - r * zc4;
            *(float4*)&arcp[(size_t)(q0 + r) * SEQ + q0 + 64 + c * 4] = z4;
        }
    }

    // ---- stage Q (64 x 64) hi/lo into smem ----
    #pragma unroll
    for (int j = 0; j < 16; j++) {
        int idx = j * 128 + tid;                      // 2048 float2
        int row = idx >> 5, c2 = idx & 31;
        float2 qv = *(const float2*)&qbase[(size_t)row * E3 + c2 * 2];
        int off = row * SQPAD + c2 * 2;
        uint32_t qh = pack_bf16(qv.x, qv.y);
        *(uint32_t*)&sQh[off] = qh;
        split_lo(qh, qv.x, qv.y, (uint32_t*)&sQl[off]);
    }
    __syncthreads();

    // ---- preload Q fragments (loop-invariant): 4 k-steps, hi/lo ----
    uint32_t qhf[4][4], qlf[4][4];
    {
        const int arow = w * 16 + (lane & 15);
        #pragma unroll
        for (int ks = 0; ks < 4; ks++) {
            const int acol = ks * 16 + (lane >> 4) * 8;
            uint32_t ad = (uint32_t)((arow * SQPAD + acol) * 2);
            ldsm4(qhf[ks], sb_qh + ad);
            ldsm4(qlf[ks], sb_ql + ad);
        }
    }

    // ---- online softmax state (per thread: 2 rows) + O accumulator ----
    const int r0 = lane >> 2;                // rows w*16 + r0, + r0+8
    float m[2] = {-INFINITY, -INFINITY}, l[2] = {0.f, 0.f};
    float o[8][4] = {};                      // m16 n64 output frags

    const int ntiles = q0 / 64 + 1;          // causal: cols < q0+64
    for (int kt = 0; kt < ntiles; kt++) {
        const int k0 = kt * 64;
        // -- load K tile (64x64) hi/lo --
        #pragma unroll
        for (int j = 0; j < 16; j++) {
            int idx = j * 128 + tid;                  // 2048 float2
            int row = idx >> 5, c2 = idx & 31;
            float2 kv = *(const float2*)&kbase[(size_t)(k0 + row) * E3 + c2 * 2];
            int off = row * SQPAD + c2 * 2;
            uint32_t kh = pack_bf16(kv.x, kv.y);
            *(uint32_t*)&sKh[off] = kh;
            split_lo(kh, kv.x, kv.y, (uint32_t*)&sKl[off]);
        }
        // -- load V tile (64x64) transposed: sV[c][k] --
        #pragma unroll
        for (int j = 0; j < 8; j++) {
            int idx = j * 128 + tid;                  // 1024 float4
            int k = idx >> 4, c4 = (idx & 15) * 4;
            float4 vv = *(const float4*)&vbase[(size_t)(k0 + k) * E3 + c4];
            #pragma unroll
            for (int e = 0; e < 4; e++) {
                float f = (&vv.x)[e];
                __nv_bfloat16 h = __float2bfloat16(f);
                sVh[(c4 + e) * SQPAD + k] = h;
                sVl[(c4 + e) * SQPAD + k] =
                    __float2bfloat16(f - __bfloat162float(h));
            }
        }
        __syncthreads();

        // -- S = Q K^T (m16 x n64, bf16x3) --
        float s[8][4] = {};
        #pragma unroll
        for (int ks = 0; ks < 4; ks++) {
            const int brow = ((lane >> 4) << 3) + (lane & 7);
            const int bcol = ks * 16 + ((lane >> 3) & 1) * 8;
            #pragma unroll
            for (int nf2 = 0; nf2 < 4; nf2++) {
                uint32_t bd = (uint32_t)(((nf2 * 16 + brow) * SQPAD + bcol) * 2);
                uint32_t bhf[4], blf[4];
                ldsm4(bhf, sb_kh + bd);
                ldsm4(blf, sb_kl + bd);
                #pragma unroll
                for (int h = 0; h < 2; h++) {
                    float* d = s[nf2 * 2 + h];
                    mma16816(d, qhf[ks], bhf + 2 * h);
                    mma16816(d, qhf[ks], blf + 2 * h);
                    mma16816(d, qlf[ks], bhf + 2 * h);
                }
            }
        }

        // -- epilogue: scale, causal+mask, arc=sigmoid, s=val|-inf --
        #pragma unroll
        for (int half = 0; half < 2; half++) {
            const int qi = q0 + w * 16 + r0 + half * 8;
            #pragma unroll
            for (int nf = 0; nf < 8; nf++) {
                const int kj = k0 + nf * 8 + (lane & 3) * 2;
                const size_t idx = (size_t)qi * SEQ + kj;
                const int2 mv = *(const int2*)&msk[idx];
                float2 og;
                #pragma unroll
                for (int e = 0; e < 2; e++) {
                    float val = s[nf][half * 2 + e] * (1.0f / 64.0f);
                    bool valid = (kj + e <= qi) && ((e ? mv.y : mv.x) != 0);
                    s[nf][half * 2 + e] = valid ? val : -INFINITY;
                    (&og.x)[e] = valid ? 1.0f / (1.0f + __expf(-val)) : 0.0f;
                }
                *(float2*)&arcp[idx] = og;
            }
        }

        // -- online softmax update --
        float alpha[2];
        #pragma unroll
        for (int i = 0; i < 2; i++) {
            float tmax = -INFINITY;
            #pragma unroll
            for (int nf = 0; nf < 8; nf++)
                tmax = fmaxf(tmax, fmaxf(s[nf][i * 2], s[nf][i * 2 + 1]));
            tmax = fmaxf(tmax, __shfl_xor_sync(0xffffffffu, tmax, 1));
            tmax = fmaxf(tmax, __shfl_xor_sync(0xffffffffu, tmax, 2));
            float mnew = fmaxf(m[i], tmax);
            alpha[i] = (m[i] == -INFINITY) ? 0.0f : __expf(m[i] - mnew);
            float tsum = 0.0f;
            #pragma unroll
            for (int nf = 0; nf < 8; nf++) {
                #pragma unroll
                for (int e = 0; e < 2; e++) {
                    float p = (mnew == -INFINITY)
                              ? 0.0f : __expf(s[nf][i * 2 + e] - mnew);
                    s[nf][i * 2 + e] = p;
                    tsum += p;
                }
            }
            tsum += __shfl_xor_sync(0xffffffffu, tsum, 1);
            tsum += __shfl_xor_sync(0xffffffffu, tsum, 2);
            l[i] = l[i] * alpha[i] + tsum;
            m[i] = mnew;
        }
        #pragma unroll
        for (int nf = 0; nf < 8; nf++) {
            o[nf][0] *= alpha[0]; o[nf][1] *= alpha[0];
            o[nf][2] *= alpha[1]; o[nf][3] *= alpha[1];
        }

        // -- P fragments (C-frag -> A-frag identity), hi/lo --
        uint32_t ph[4][4], pl[4][4];
        #pragma unroll
        for (int j = 0; j < 4; j++) {
            const float* e0 = s[2 * j];      // k = j*16 + (lane&3)*2 (+1)
            const float* e1 = s[2 * j + 1];  // k = +8
            ph[j][0] = pack_bf16(e0[0], e0[1]);
            split_lo(ph[j][0], e0[0], e0[1], &pl[j][0]);
            ph[j][1] = pack_bf16(e0[2], e0[3]);
            split_lo(ph[j][1], e0[2], e0[3], &pl[j][1]);
            ph[j][2] = pack_bf16(e1[0], e1[1]);
            split_lo(ph[j][2], e1[0], e1[1], &pl[j][2]);
            ph[j][3] = pack_bf16(e1[2], e1[3]);
            split_lo(ph[j][3], e1[2], e1[3], &pl[j][3]);
        }

        // -- O += P V  (m16 n64 k64, bf16x3) --
        #pragma unroll
        for (int j = 0; j < 4; j++) {        // k-steps over P's 64 keys
            const int brow = ((lane >> 4) << 3) + (lane & 7);
            const int bcol = j * 16 + ((lane >> 3) & 1) * 8;
            #pragma unroll
            for (int nf2 = 0; nf2 < 4; nf2++) {
                uint32_t bd = (uint32_t)(((nf2 * 16 + brow) * SQPAD + bcol) * 2);
                uint32_t bhf[4], blf[4];
                ldsm4(bhf, sb_vh + bd);
                ldsm4(blf, sb_vl + bd);
                #pragma unroll
                for (int h = 0; h < 2; h++) {
                    float* d = o[nf2 * 2 + h];
                    mma16816(d, ph[j], bhf + 2 * h);
                    mma16816(d, ph[j], blf + 2 * h);
                    mma16816(d, pl[j], bhf + 2 * h);
                }
            }
        }
        __syncthreads();
    }

    // ---- normalize and write O ----
    const float inv0 = (l[0] > 0.f) ? 1.0f / l[0] : 0.0f;
    const float inv1 = (l[1] > 0.f) ? 1.0f / l[1] : 0.0f;
    const int r = q0 + w * 16 + r0;
    #pragma unroll
    for (int nf = 0; nf < 8; nf++) {
        const int c = head * HD + nf * 8 + (lane & 3) * 2;
        *(float2*)&g_ao[(size_t)(b * SEQ + r) * EMB + c] =
            make_float2(o[nf][0] * inv0, o[nf][1] * inv0);
        *(float2*)&g_ao[(size_t)(b * SEQ + r + 8) * EMB + c] =
            make_float2(o[nf][2] * inv1, o[nf][3] * inv1);
    }
}

// ---------------- launch ----------------------------------------------------
extern "C" void kernel_launch(void* const* d_in, const int* in_sizes, int n_in,
                              void* d_out, int out_size) {
    const float* x      = (const float*)d_in[0];
    const float* w_qkv  = (const float*)d_in[1];
    const float* w_proj = (const float*)d_in[2];
    const int*   m_head  = (const int*)d_in[3];
    const int*   m_child = (const int*)d_in[4];

    float* out = (float*)d_out;
    float* arc = out + (size_t)BATCH * SEQ * EMB;

    float *p_qkv, *p_ao;
    cudaGetSymbolAddress((void**)&p_qkv, g_qkv);
    cudaGetSymbolAddress((void**)&p_ao,  g_ao);

    cudaFuncSetAttribute(flash_att,
                         cudaFuncAttributeMaxDynamicSharedMemorySize, FO_TOTAL);

    // 1) QKV = X @ Wqkv^T : [2048,3072]  (bf16x3 mma.sync)
    gemm_mma<<<dim3(E3 / 128, BATCH * SEQ / 128), 256>>>(
        x, w_qkv, p_qkv, E3, EMB);

    // 2) fused: scores + mask + sigmoid(arc) + online softmax + P@V
    flash_att<<<dim3(SEQ / 64, BATCH * MHEAD), 128, FO_TOTAL>>>(
        m_head, m_child, arc);

    // 3) out = AO @ Wproj^T  (bf16x3 mma.sync)
    gemm_mma<<<dim3(EMB / 128, BATCH * SEQ / 128), 256>>>(
        p_ao, w_proj, out, EMB, EMB);
}